// round 15
// baseline (speedup 1.0000x reference)
#include <cuda_runtime.h>
#include <cuda_bf16.h>
#include <cuda_fp16.h>
#include <cstddef>
#include <cstdint>

#define NS 128
#define DD 128
#define NB 16
#define NT 4096
#define NCH 16          // chunks over t in [1, NT)
#define LCH 256         // nominal chunk length
#define SP 136          // padded row stride (f16 elems) for G buffers
#define LOG2PI 1.8378770664093453f
#define LOG128 4.852030263919617f

#define FMA2(d, a, b) asm("fma.rn.f32x2 %0, %1, %2, %0;" : "+l"(d) : "l"(a), "l"(b))
// packed f16x2: lo = a, hi = b
#define CVTH(res, a, b) asm("cvt.rn.f16x2.f32 %0, %1, %2;" : "=r"(res) : "f"(b), "f"(a))
#define MULH2(res, a, b) asm("mul.rn.f16x2 %0, %1, %2;" : "=r"(res) : "r"(a), "r"(b))

// f16 in / f16 accumulate — 2x rate vs f32-accum on legacy HMMA path
#define MMAH(D, A, B0, B1) \
    asm volatile("mma.sync.aligned.m16n8k16.row.col.f16.f16.f16.f16 " \
        "{%0,%1}, {%2,%3,%4,%5}, {%6,%7}, {%0,%1};" \
        : "+r"((D)[0]), "+r"((D)[1]) \
        : "r"((A)[0]), "r"((A)[1]), "r"((A)[2]), "r"((A)[3]), "r"(B0), "r"(B1))

#define LDSM4(r0, r1, r2, r3, addr) \
    asm volatile("ldmatrix.sync.aligned.m8n8.x4.shared.b16 {%0,%1,%2,%3}, [%4];" \
        : "=r"(r0), "=r"(r1), "=r"(r2), "=r"(r3) : "r"(addr))

// ---------------- scratch (static device globals; no allocation) ----------------
__device__ float g_A[NS * NS];                 // A'[i*128+j] = softmax(transition, axis=1)
__device__ float g_pi[NS];
__device__ float2 g_UV[DD * NS];               // [d][n]: (mu*inv_var, -0.5*inv_var)
__device__ float g_c2[NS];
__device__ float g_w[(size_t)NB * NT * NS];    // w[b][t][n] = exp(e-emax)*128/Z
__device__ float g_o[NB * NT];
__device__ float g_So[NB];
__device__ float g_res[NB];
__device__ __half g_M[(size_t)NB * NCH * NS * NS];  // chunk matrices (row-major)

__device__ __forceinline__ uint32_t s2u(const void* p) {
    uint32_t a;
    asm("{ .reg .u64 t; cvta.to.shared.u64 t, %1; cvt.u32.u64 %0, t; }" : "=r"(a) : "l"(p));
    return a;
}

// ---------------- kernel A: parameter prep (128 CTAs) ----------------
__global__ void prep_kernel(const float* __restrict__ trans,
                            const float* __restrict__ priors,
                            const float* __restrict__ means,
                            const float* __restrict__ scales) {
    int n = blockIdx.x;
    int k = threadIdx.x;
    __shared__ float red[128];

    float v = trans[n * NS + k];
    red[k] = v; __syncthreads();
    for (int s = 64; s; s >>= 1) { if (k < s) red[k] = fmaxf(red[k], red[k + s]); __syncthreads(); }
    float m = red[0]; __syncthreads();
    float e = expf(v - m);
    red[k] = e; __syncthreads();
    for (int s = 64; s; s >>= 1) { if (k < s) red[k] += red[k + s]; __syncthreads(); }
    g_A[n * NS + k] = e / red[0];
    __syncthreads();

    float pv = priors[k];
    red[k] = pv; __syncthreads();
    for (int s = 64; s; s >>= 1) { if (k < s) red[k] = fmaxf(red[k], red[k + s]); __syncthreads(); }
    float pm = red[0]; __syncthreads();
    float pe = expf(pv - pm);
    red[k] = pe; __syncthreads();
    for (int s = 64; s; s >>= 1) { if (k < s) red[k] += red[k + s]; __syncthreads(); }
    if (k == n) g_pi[n] = pe / red[0];
    __syncthreads();

    float sr = scales[n * DD + k];
    float var = (sr > 20.f) ? sr : log1pf(expf(sr));
    var += 1e-6f;
    float inv = 1.f / var;
    float mu = means[n * DD + k];
    g_UV[k * NS + n] = make_float2(mu * inv, -0.5f * inv);
    float acc = mu * mu * inv + logf(var);
    red[k] = acc; __syncthreads();
    for (int s = 64; s; s >>= 1) { if (k < s) red[k] += red[k + s]; __syncthreads(); }
    if (k == 0) g_c2[n] = -0.5f * (red[0] + (float)DD * LOG2PI);
}

// ---------------- kernel B: emission GEMM (packed f32x2) + fused softmax ----------------
__global__ __launch_bounds__(256) void emis_kernel(const float* __restrict__ X) {
    __shared__ float2 xq[32][38];
    __shared__ float2 uvs[32][128];

    int b  = blockIdx.x >> 7;
    int t0 = (blockIdx.x & 127) << 5;
    int tid = threadIdx.x;
    int tx = tid & 31;
    int ty = tid >> 5;

    unsigned long long acc2[16];
#pragma unroll
    for (int i = 0; i < 16; i++) acc2[i] = 0ull;

    const float* Xbase = X + ((size_t)(b * NT + t0)) * DD;

    for (int kb = 0; kb < 4; kb++) {
        int d0 = kb * 32;
        {
            int r = tid >> 3;
            int dd0 = (tid & 7) << 2;
            float4 xv = *(const float4*)(Xbase + (size_t)r * DD + d0 + dd0);
            xq[dd0 + 0][r] = make_float2(xv.x, xv.x * xv.x);
            xq[dd0 + 1][r] = make_float2(xv.y, xv.y * xv.y);
            xq[dd0 + 2][r] = make_float2(xv.z, xv.z * xv.z);
            xq[dd0 + 3][r] = make_float2(xv.w, xv.w * xv.w);
        }
        {
            const float4* src = (const float4*)(g_UV + d0 * NS);
            float4* dst = (float4*)&uvs[0][0];
            for (int i = tid; i < 2048; i += 256) dst[i] = src[i];
        }
        __syncthreads();

#pragma unroll
        for (int dd = 0; dd < 32; dd++) {
            ulonglong2 x01 = *(const ulonglong2*)&xq[dd][4 * ty];
            ulonglong2 x23 = *(const ulonglong2*)&xq[dd][4 * ty + 2];
            unsigned long long px[4] = {x01.x, x01.y, x23.x, x23.y};
            unsigned long long pu[4];
            pu[0] = *(const unsigned long long*)&uvs[dd][tx];
            pu[1] = *(const unsigned long long*)&uvs[dd][tx + 32];
            pu[2] = *(const unsigned long long*)&uvs[dd][tx + 64];
            pu[3] = *(const unsigned long long*)&uvs[dd][tx + 96];
#pragma unroll
            for (int r = 0; r < 4; r++)
#pragma unroll
                for (int c = 0; c < 4; c++)
                    FMA2(acc2[r * 4 + c], px[r], pu[c]);
        }
        __syncthreads();
    }

    float c2a[4];
    c2a[0] = g_c2[tx];      c2a[1] = g_c2[tx + 32];
    c2a[2] = g_c2[tx + 64]; c2a[3] = g_c2[tx + 96];

#pragma unroll
    for (int rr = 0; rr < 4; rr++) {
        float e[4];
#pragma unroll
        for (int c = 0; c < 4; c++) {
            float lo, hi;
            asm("mov.b64 {%0,%1}, %2;" : "=f"(lo), "=f"(hi) : "l"(acc2[rr * 4 + c]));
            e[c] = lo + hi + c2a[c];
        }
        float m = fmaxf(fmaxf(e[0], e[1]), fmaxf(e[2], e[3]));
#pragma unroll
        for (int off = 16; off; off >>= 1)
            m = fmaxf(m, __shfl_xor_sync(0xffffffffu, m, off));
        float w0 = expf(e[0] - m), w1 = expf(e[1] - m);
        float w2 = expf(e[2] - m), w3 = expf(e[3] - m);
        float z = (w0 + w1) + (w2 + w3);
#pragma unroll
        for (int off = 16; off; off >>= 1)
            z += __shfl_xor_sync(0xffffffffu, z, off);
        float sc = 128.f / z;
        int t = t0 + 4 * ty + rr;
        float* wrow = g_w + ((size_t)(b * NT + t)) * NS;
        wrow[tx]      = w0 * sc;
        wrow[tx + 32] = w1 * sc;
        wrow[tx + 64] = w2 * sc;
        wrow[tx + 96] = w3 * sc;
        if (tx == 0) g_o[b * NT + t] = m + logf(z) - LOG128;
    }
}

// ---------------- kernel C: per-batch offset sums ----------------
__global__ void off_kernel() {
    int b = blockIdx.x;
    __shared__ float sh[8];
    int tid = threadIdx.x;
    float s = 0.f;
    for (int t = tid; t < NT; t += 256) s += g_o[b * NT + t];
#pragma unroll
    for (int off = 16; off; off >>= 1) s += __shfl_xor_sync(0xffffffffu, s, off);
    if ((tid & 31) == 0) sh[tid >> 5] = s;
    __syncthreads();
    if (tid == 0) {
        float tot = 0.f;
#pragma unroll
        for (int k = 0; k < 8; k++) tot += sh[k];
        g_So[b] = tot;
    }
}

// ---------------- kernel D: chunk composition via mma.sync f16 (2x HMMA rate) ----------------
// 256 CTAs x 128 threads. CTA = (b, c):
//   G_0 = A*diag(w_{t0});  step s: G <- (G @ A) * colscale(w)
__global__ __launch_bounds__(128, 1) void comp_kernel() {
    extern __shared__ char smd[];
    float* wsm = (float*)smd;                                  // [2][128]
    __half* gptr0 = (__half*)(smd + 1024);
    __half* gptr1 = (__half*)(smd + 1024 + 2 * NS * SP);
    uint32_t gb0 = s2u(gptr0), gb1 = s2u(gptr1);

    int tid = threadIdx.x;
    int lane = tid & 31;
    int wrp = tid >> 5;
    int wm = wrp & 1;          // m-half: rows [64wm, 64wm+64)
    int wn = wrp >> 1;         // n-half: cols [64wn, 64wn+64)
    int b = blockIdx.x >> 4;
    int c = blockIdx.x & 15;
    int t0 = 1 + LCH * c;
    int nst = NT - t0; if (nst > LCH) nst = LCH;
    int comps = nst - 1;
    int tmax = t0 + comps;
    const float* wb = g_w + (size_t)b * NT * NS;

    // ---- static B fragments (f16): B[kt][nt] covers A[16kt:16kt+16][64wn+8nt : +8] ----
    uint32_t B[8][8][2];
    {
        int n = 64 * wn + (lane >> 2);
        int k0 = 2 * (lane & 3);
#pragma unroll
        for (int kt = 0; kt < 8; kt++)
#pragma unroll
            for (int nt = 0; nt < 8; nt++) {
                int kk = 16 * kt + k0;
                int nn = n + 8 * nt;
                CVTH(B[kt][nt][0], g_A[kk * NS + nn], g_A[(kk + 1) * NS + nn]);
                CVTH(B[kt][nt][1], g_A[(kk + 8) * NS + nn], g_A[(kk + 9) * NS + nn]);
            }
    }

    // stage w_{t0} -> wsm[0], w_{t0+1} -> wsm[1]
    wsm[tid] = wb[(size_t)t0 * NS + tid];
    wsm[128 + tid] = wb[(size_t)(t0 + 1) * NS + tid];
    __syncthreads();

    // ---- G_0[r][c] = A[r][c] * w_{t0}[c]; thread handles row tid ----
    {
        const float4* arow = (const float4*)(g_A + tid * NS);
        uint4* grow = (uint4*)(gptr0 + tid * SP);
#pragma unroll
        for (int i = 0; i < 16; i++) {
            float4 a0 = arow[2 * i];
            float4 a1 = arow[2 * i + 1];
            const float4* wv4 = (const float4*)(wsm + 8 * i);
            float4 v0 = wv4[0], v1 = wv4[1];
            uint32_t p0, p1, p2, p3;
            CVTH(p0, a0.x * v0.x, a0.y * v0.y);
            CVTH(p1, a0.z * v0.z, a0.w * v0.w);
            CVTH(p2, a1.x * v1.x, a1.y * v1.y);
            CVTH(p3, a1.z * v1.z, a1.w * v1.w);
            grow[i] = make_uint4(p0, p1, p2, p3);
        }
    }
    int tpre = t0 + 2; if (tpre > tmax) tpre = tmax;
    float wreg = wb[(size_t)tpre * NS + tid];
    __syncthreads();

    uint32_t lrow = (uint32_t)((lane & 7) + ((lane >> 3) & 1) * 8);
    uint32_t lcol8 = (uint32_t)((lane >> 4) * 8);

    for (int s = 0; s < comps; s++) {
        wsm[(s & 1) * 128 + tid] = wreg;
        int tl = t0 + 3 + s; if (tl > tmax) tl = tmax;
        wreg = wb[(size_t)tl * NS + tid];

        uint32_t gc = (s & 1) ? gb1 : gb0;
        __half* gn = (s & 1) ? gptr0 : gptr1;
        const float* wrow = wsm + ((s + 1) & 1) * 128;

#pragma unroll
        for (int mt = 0; mt < 4; mt++) {
            int mb = 64 * wm + 16 * mt;
            uint32_t a[8][4];
#pragma unroll
            for (int kt = 0; kt < 8; kt++) {
                uint32_t addr = gc + (((uint32_t)(mb) + lrow) * SP + 16u * kt + lcol8) * 2u;
                LDSM4(a[kt][0], a[kt][1], a[kt][2], a[kt][3], addr);
            }
            uint32_t d[8][2];
#pragma unroll
            for (int nt = 0; nt < 8; nt++) { d[nt][0] = 0u; d[nt][1] = 0u; }
#pragma unroll
            for (int kt = 0; kt < 8; kt++)
#pragma unroll
                for (int nt = 0; nt < 8; nt++)
                    MMAH(d[nt], a[kt], B[kt][nt][0], B[kt][nt][1]);

            // epilogue: scale cols by w (f16x2), store
            int r0 = mb + (lane >> 2);
#pragma unroll
            for (int nt = 0; nt < 8; nt++) {
                int c0 = 64 * wn + 8 * nt + 2 * (lane & 3);
                float2 wp = *(const float2*)(wrow + c0);
                uint32_t wp2, p0, p1;
                CVTH(wp2, wp.x, wp.y);
                MULH2(p0, d[nt][0], wp2);
                MULH2(p1, d[nt][1], wp2);
                *(uint32_t*)(gn + r0 * SP + c0) = p0;
                *(uint32_t*)(gn + (r0 + 8) * SP + c0) = p1;
            }
        }
        __syncthreads();
    }

    // ---- write final G to global (row-major f16) ----
    {
        const uint4* src = (const uint4*)(((comps & 1) ? gptr1 : gptr0) + tid * SP);
        uint4* dst = (uint4*)(g_M + ((size_t)(b * NCH + c) << 14) + (size_t)tid * NS);
#pragma unroll
        for (int i = 0; i < 16; i++) dst[i] = src[i];
    }
}

// ---------------- kernel E: cross-chunk combine ----------------
__global__ __launch_bounds__(128) void comb_kernel() {
    int b = blockIdx.x;
    int j = threadIdx.x;
    __shared__ float Ps[NS];
    Ps[j] = g_pi[j] * g_w[(size_t)b * NT * NS + j];
    __syncthreads();
    for (int c = 0; c < NCH; c++) {
        const __half* G = g_M + ((size_t)(b * NCH + c) << 14);
        float s = 0.f;
#pragma unroll 8
        for (int i = 0; i < NS; i++)
            s += __half2float(G[(size_t)i * NS + j]) * Ps[i];
        __syncthreads();
        Ps[j] = s;
        __syncthreads();
    }
    float v = Ps[j];
#pragma unroll
    for (int off = 16; off; off >>= 1) v += __shfl_xor_sync(0xffffffffu, v, off);
    __shared__ float ws[4];
    if ((j & 31) == 0) ws[j >> 5] = v;
    __syncthreads();
    if (j == 0) g_res[b] = logf(((ws[0] + ws[1]) + (ws[2] + ws[3]))) + g_So[b];
}

// ---------------- kernel F: final sum over batches ----------------
__global__ void fin_kernel(float* out) {
    if (threadIdx.x == 0) {
        float s = 0.f;
        for (int b = 0; b < NB; b++) s += g_res[b];
        out[0] = s;
    }
}

// ---------------- launch ----------------
extern "C" void kernel_launch(void* const* d_in, const int* in_sizes, int n_in,
                              void* d_out, int out_size) {
    const float* X      = (const float*)d_in[0];
    const float* trans  = (const float*)d_in[1];
    const float* priors = (const float*)d_in[2];
    const float* means  = (const float*)d_in[3];
    const float* scales = (const float*)d_in[4];

    int smem = 1024 + 2 * NS * SP * 2;   // wbuf + two G buffers
    cudaFuncSetAttribute(comp_kernel, cudaFuncAttributeMaxDynamicSharedMemorySize, smem);

    prep_kernel<<<NS, 128>>>(trans, priors, means, scales);
    emis_kernel<<<2048, 256>>>(X);
    off_kernel<<<NB, 256>>>();
    comp_kernel<<<NB * NCH, 128, smem>>>();
    comb_kernel<<<NB, 128>>>();
    fin_kernel<<<1, 32>>>((float*)d_out);
}

// round 16
// speedup vs baseline: 1.6127x; 1.6127x over previous
#include <cuda_runtime.h>
#include <cuda_bf16.h>
#include <cstddef>
#include <cstdint>

#define NS 128
#define DD 128
#define NB 16
#define NT 4096
#define NCH 18          // chunks over t in [1, NT)
#define LCH 228         // chunk length (18*228 >= 4095)
#define SP 136          // padded row stride (bf16 elems) for G buffers
#define LOG2PI 1.8378770664093453f
#define LOG128 4.852030263919617f

#define FMA2(d, a, b) asm("fma.rn.f32x2 %0, %1, %2, %0;" : "+l"(d) : "l"(a), "l"(b))
// packed bf16x2: lo = a, hi = b
#define CVTP(res, a, b) asm("cvt.rn.satfinite.bf16x2.f32 %0, %1, %2;" : "=r"(res) : "f"(b), "f"(a))

#define MMA16816(D, A, B0, B1) \
    asm volatile("mma.sync.aligned.m16n8k16.row.col.f32.bf16.bf16.f32 " \
        "{%0,%1,%2,%3}, {%4,%5,%6,%7}, {%8,%9}, {%0,%1,%2,%3};" \
        : "+f"((D)[0]), "+f"((D)[1]), "+f"((D)[2]), "+f"((D)[3]) \
        : "r"((A)[0]), "r"((A)[1]), "r"((A)[2]), "r"((A)[3]), "r"(B0), "r"(B1))

#define LDSM4(r0, r1, r2, r3, addr) \
    asm volatile("ldmatrix.sync.aligned.m8n8.x4.shared.b16 {%0,%1,%2,%3}, [%4];" \
        : "=r"(r0), "=r"(r1), "=r"(r2), "=r"(r3) : "r"(addr))

// ---------------- scratch (static device globals; no allocation) ----------------
__device__ float g_A[NS * NS];                 // A'[i*128+j] = softmax(transition, axis=1)
__device__ float g_pi[NS];
__device__ float2 g_UV[DD * NS];               // [d][n]: (mu*inv_var, -0.5*inv_var)
__device__ float g_c2[NS];
__device__ float g_w[(size_t)NB * NT * NS];    // w[b][t][n] = exp(e-emax)*128/Z
__device__ float g_o[NB * NT];
__device__ float g_So[NB];
__device__ float g_res[NB];
__device__ __nv_bfloat16 g_M[(size_t)NB * NCH * NS * NS];  // chunk matrices (row-major)

__device__ __forceinline__ uint32_t s2u(const void* p) {
    uint32_t a;
    asm("{ .reg .u64 t; cvta.to.shared.u64 t, %1; cvt.u32.u64 %0, t; }" : "=r"(a) : "l"(p));
    return a;
}

// ---------------- kernel A: parameter prep (128 CTAs) ----------------
__global__ void prep_kernel(const float* __restrict__ trans,
                            const float* __restrict__ priors,
                            const float* __restrict__ means,
                            const float* __restrict__ scales) {
    int n = blockIdx.x;
    int k = threadIdx.x;
    __shared__ float red[128];

    float v = trans[n * NS + k];
    red[k] = v; __syncthreads();
    for (int s = 64; s; s >>= 1) { if (k < s) red[k] = fmaxf(red[k], red[k + s]); __syncthreads(); }
    float m = red[0]; __syncthreads();
    float e = expf(v - m);
    red[k] = e; __syncthreads();
    for (int s = 64; s; s >>= 1) { if (k < s) red[k] += red[k + s]; __syncthreads(); }
    g_A[n * NS + k] = e / red[0];
    __syncthreads();

    float pv = priors[k];
    red[k] = pv; __syncthreads();
    for (int s = 64; s; s >>= 1) { if (k < s) red[k] = fmaxf(red[k], red[k + s]); __syncthreads(); }
    float pm = red[0]; __syncthreads();
    float pe = expf(pv - pm);
    red[k] = pe; __syncthreads();
    for (int s = 64; s; s >>= 1) { if (k < s) red[k] += red[k + s]; __syncthreads(); }
    if (k == n) g_pi[n] = pe / red[0];
    __syncthreads();

    float sr = scales[n * DD + k];
    float var = (sr > 20.f) ? sr : log1pf(expf(sr));
    var += 1e-6f;
    float inv = 1.f / var;
    float mu = means[n * DD + k];
    g_UV[k * NS + n] = make_float2(mu * inv, -0.5f * inv);
    float acc = mu * mu * inv + logf(var);
    red[k] = acc; __syncthreads();
    for (int s = 64; s; s >>= 1) { if (k < s) red[k] += red[k + s]; __syncthreads(); }
    if (k == 0) g_c2[n] = -0.5f * (red[0] + (float)DD * LOG2PI);
}

// ---------------- kernel B: emission GEMM (packed f32x2) + fused softmax ----------------
__global__ __launch_bounds__(256) void emis_kernel(const float* __restrict__ X) {
    __shared__ float2 xq[32][38];
    __shared__ float2 uvs[32][128];

    int b  = blockIdx.x >> 7;
    int t0 = (blockIdx.x & 127) << 5;
    int tid = threadIdx.x;
    int tx = tid & 31;
    int ty = tid >> 5;

    unsigned long long acc2[16];
#pragma unroll
    for (int i = 0; i < 16; i++) acc2[i] = 0ull;

    const float* Xbase = X + ((size_t)(b * NT + t0)) * DD;

    for (int kb = 0; kb < 4; kb++) {
        int d0 = kb * 32;
        {
            int r = tid >> 3;
            int dd0 = (tid & 7) << 2;
            float4 xv = *(const float4*)(Xbase + (size_t)r * DD + d0 + dd0);
            xq[dd0 + 0][r] = make_float2(xv.x, xv.x * xv.x);
            xq[dd0 + 1][r] = make_float2(xv.y, xv.y * xv.y);
            xq[dd0 + 2][r] = make_float2(xv.z, xv.z * xv.z);
            xq[dd0 + 3][r] = make_float2(xv.w, xv.w * xv.w);
        }
        {
            const float4* src = (const float4*)(g_UV + d0 * NS);
            float4* dst = (float4*)&uvs[0][0];
            for (int i = tid; i < 2048; i += 256) dst[i] = src[i];
        }
        __syncthreads();

#pragma unroll
        for (int dd = 0; dd < 32; dd++) {
            ulonglong2 x01 = *(const ulonglong2*)&xq[dd][4 * ty];
            ulonglong2 x23 = *(const ulonglong2*)&xq[dd][4 * ty + 2];
            unsigned long long px[4] = {x01.x, x01.y, x23.x, x23.y};
            unsigned long long pu[4];
            pu[0] = *(const unsigned long long*)&uvs[dd][tx];
            pu[1] = *(const unsigned long long*)&uvs[dd][tx + 32];
            pu[2] = *(const unsigned long long*)&uvs[dd][tx + 64];
            pu[3] = *(const unsigned long long*)&uvs[dd][tx + 96];
#pragma unroll
            for (int r = 0; r < 4; r++)
#pragma unroll
                for (int c = 0; c < 4; c++)
                    FMA2(acc2[r * 4 + c], px[r], pu[c]);
        }
        __syncthreads();
    }

    float c2a[4];
    c2a[0] = g_c2[tx];      c2a[1] = g_c2[tx + 32];
    c2a[2] = g_c2[tx + 64]; c2a[3] = g_c2[tx + 96];

#pragma unroll
    for (int rr = 0; rr < 4; rr++) {
        float e[4];
#pragma unroll
        for (int c = 0; c < 4; c++) {
            float lo, hi;
            asm("mov.b64 {%0,%1}, %2;" : "=f"(lo), "=f"(hi) : "l"(acc2[rr * 4 + c]));
            e[c] = lo + hi + c2a[c];
        }
        float m = fmaxf(fmaxf(e[0], e[1]), fmaxf(e[2], e[3]));
#pragma unroll
        for (int off = 16; off; off >>= 1)
            m = fmaxf(m, __shfl_xor_sync(0xffffffffu, m, off));
        float w0 = expf(e[0] - m), w1 = expf(e[1] - m);
        float w2 = expf(e[2] - m), w3 = expf(e[3] - m);
        float z = (w0 + w1) + (w2 + w3);
#pragma unroll
        for (int off = 16; off; off >>= 1)
            z += __shfl_xor_sync(0xffffffffu, z, off);
        float sc = 128.f / z;
        int t = t0 + 4 * ty + rr;
        float* wrow = g_w + ((size_t)(b * NT + t)) * NS;
        wrow[tx]      = w0 * sc;
        wrow[tx + 32] = w1 * sc;
        wrow[tx + 64] = w2 * sc;
        wrow[tx + 96] = w3 * sc;
        if (tx == 0) g_o[b * NT + t] = m + logf(z) - LOG128;
    }
}

// ---------------- kernel C: per-batch offset sums ----------------
__global__ void off_kernel() {
    int b = blockIdx.x;
    __shared__ float sh[8];
    int tid = threadIdx.x;
    float s = 0.f;
    for (int t = tid; t < NT; t += 256) s += g_o[b * NT + t];
#pragma unroll
    for (int off = 16; off; off >>= 1) s += __shfl_xor_sync(0xffffffffu, s, off);
    if ((tid & 31) == 0) sh[tid >> 5] = s;
    __syncthreads();
    if (tid == 0) {
        float tot = 0.f;
#pragma unroll
        for (int k = 0; k < 8; k++) tot += sh[k];
        g_So[b] = tot;
    }
}

// ---------------- kernel D: chunk composition via mma.sync (HMMA bf16, f32 acc) ----------------
// 288 CTAs x 128 threads. CTA = (b, c):
//   G_0 = A*diag(w_{t0});  step s: G <- (G @ A) * colscale(w)
// Warp layout: warp wrp owns n-cols [32*wrp, 32*wrp+32) (4 nt); mt loops all 8 row tiles.
// B-frags 64 regs/warp (was 128) -> no spills.
__global__ __launch_bounds__(128, 1) void comp_kernel() {
    extern __shared__ char smd[];
    float* wsm = (float*)smd;                                  // [2][128]
    __nv_bfloat16* gptr0 = (__nv_bfloat16*)(smd + 1024);
    __nv_bfloat16* gptr1 = (__nv_bfloat16*)(smd + 1024 + 2 * NS * SP);
    uint32_t gb0 = s2u(gptr0), gb1 = s2u(gptr1);

    int tid = threadIdx.x;
    int lane = tid & 31;
    int wrp = tid >> 5;        // n-quarter: cols [32*wrp, 32*wrp+32)
    int b = blockIdx.x / NCH;
    int c = blockIdx.x % NCH;
    int t0 = 1 + LCH * c;
    int nst = NT - t0; if (nst > LCH) nst = LCH;
    int comps = nst - 1;
    int tmax = t0 + comps;
    const float* wb = g_w + (size_t)b * NT * NS;

    // ---- static B fragments: B[kt][nt] covers A[16kt:16kt+16][32*wrp+8nt : +8] ----
    uint32_t B[8][4][2];
    {
        int n = 32 * wrp + (lane >> 2);
        int k0 = 2 * (lane & 3);
#pragma unroll
        for (int kt = 0; kt < 8; kt++)
#pragma unroll
            for (int nt = 0; nt < 4; nt++) {
                int kk = 16 * kt + k0;
                int nn = n + 8 * nt;
                CVTP(B[kt][nt][0], g_A[kk * NS + nn], g_A[(kk + 1) * NS + nn]);
                CVTP(B[kt][nt][1], g_A[(kk + 8) * NS + nn], g_A[(kk + 9) * NS + nn]);
            }
    }

    // stage w_{t0} -> wsm[0], w_{t0+1} -> wsm[1]
    wsm[tid] = wb[(size_t)t0 * NS + tid];
    wsm[128 + tid] = wb[(size_t)(t0 + 1) * NS + tid];
    __syncthreads();

    // ---- G_0[r][c] = A[r][c] * w_{t0}[c]; thread handles row tid ----
    {
        const float4* arow = (const float4*)(g_A + tid * NS);
        uint4* grow = (uint4*)(gptr0 + tid * SP);
#pragma unroll
        for (int i = 0; i < 16; i++) {
            float4 a0 = arow[2 * i];
            float4 a1 = arow[2 * i + 1];
            const float4* wv4 = (const float4*)(wsm + 8 * i);
            float4 v0 = wv4[0], v1 = wv4[1];
            uint32_t p0, p1, p2, p3;
            CVTP(p0, a0.x * v0.x, a0.y * v0.y);
            CVTP(p1, a0.z * v0.z, a0.w * v0.w);
            CVTP(p2, a1.x * v1.x, a1.y * v1.y);
            CVTP(p3, a1.z * v1.z, a1.w * v1.w);
            grow[i] = make_uint4(p0, p1, p2, p3);
        }
    }
    int tpre = t0 + 2; if (tpre > tmax) tpre = tmax;
    float wreg = wb[(size_t)tpre * NS + tid];
    __syncthreads();

    uint32_t lrow = (uint32_t)((lane & 7) + ((lane >> 3) & 1) * 8);
    uint32_t lcol8 = (uint32_t)((lane >> 4) * 8);

    for (int s = 0; s < comps; s++) {
        wsm[(s & 1) * 128 + tid] = wreg;
        int tl = t0 + 3 + s; if (tl > tmax) tl = tmax;
        wreg = wb[(size_t)tl * NS + tid];

        uint32_t gc = (s & 1) ? gb1 : gb0;
        __nv_bfloat16* gn = (s & 1) ? gptr0 : gptr1;
        const float* wrow = wsm + ((s + 1) & 1) * 128;

#pragma unroll
        for (int mt = 0; mt < 8; mt++) {
            int mb = 16 * mt;
            uint32_t a[8][4];
#pragma unroll
            for (int kt = 0; kt < 8; kt++) {
                uint32_t addr = gc + (((uint32_t)(mb) + lrow) * SP + 16u * kt + lcol8) * 2u;
                LDSM4(a[kt][0], a[kt][1], a[kt][2], a[kt][3], addr);
            }
            float d[4][4];
#pragma unroll
            for (int nt = 0; nt < 4; nt++) {
                d[nt][0] = 0.f; d[nt][1] = 0.f; d[nt][2] = 0.f; d[nt][3] = 0.f;
            }
#pragma unroll
            for (int kt = 0; kt < 8; kt++)
#pragma unroll
                for (int nt = 0; nt < 4; nt++)
                    MMA16816(d[nt], a[kt], B[kt][nt][0], B[kt][nt][1]);

            // epilogue: scale cols by w, cvt bf16, store to G_new
            int r0 = mb + (lane >> 2);
#pragma unroll
            for (int nt = 0; nt < 4; nt++) {
                int c0 = 32 * wrp + 8 * nt + 2 * (lane & 3);
                float2 wp = *(const float2*)(wrow + c0);
                uint32_t p0, p1;
                CVTP(p0, d[nt][0] * wp.x, d[nt][1] * wp.y);
                CVTP(p1, d[nt][2] * wp.x, d[nt][3] * wp.y);
                *(uint32_t*)(gn + r0 * SP + c0) = p0;
                *(uint32_t*)(gn + (r0 + 8) * SP + c0) = p1;
            }
        }
        __syncthreads();
    }

    // ---- write final G to global (row-major bf16) ----
    {
        const uint4* src = (const uint4*)(((comps & 1) ? gptr1 : gptr0) + tid * SP);
        uint4* dst = (uint4*)(g_M + ((size_t)(b * NCH + c) << 14) + (size_t)tid * NS);
#pragma unroll
        for (int i = 0; i < 16; i++) dst[i] = src[i];
    }
}

// ---------------- kernel E: cross-chunk combine ----------------
__global__ __launch_bounds__(128) void comb_kernel() {
    int b = blockIdx.x;
    int j = threadIdx.x;
    __shared__ float Ps[NS];
    Ps[j] = g_pi[j] * g_w[(size_t)b * NT * NS + j];
    __syncthreads();
    for (int c = 0; c < NCH; c++) {
        const __nv_bfloat16* G = g_M + ((size_t)(b * NCH + c) << 14);
        float s = 0.f;
#pragma unroll 8
        for (int i = 0; i < NS; i++)
            s += __bfloat162float(G[(size_t)i * NS + j]) * Ps[i];
        __syncthreads();
        Ps[j] = s;
        __syncthreads();
    }
    float v = Ps[j];
#pragma unroll
    for (int off = 16; off; off >>= 1) v += __shfl_xor_sync(0xffffffffu, v, off);
    __shared__ float ws[4];
    if ((j & 31) == 0) ws[j >> 5] = v;
    __syncthreads();
    if (j == 0) g_res[b] = logf(((ws[0] + ws[1]) + (ws[2] + ws[3]))) + g_So[b];
}

// ---------------- kernel F: final sum over batches ----------------
__global__ void fin_kernel(float* out) {
    if (threadIdx.x == 0) {
        float s = 0.f;
        for (int b = 0; b < NB; b++) s += g_res[b];
        out[0] = s;
    }
}

// ---------------- launch ----------------
extern "C" void kernel_launch(void* const* d_in, const int* in_sizes, int n_in,
                              void* d_out, int out_size) {
    const float* X      = (const float*)d_in[0];
    const float* trans  = (const float*)d_in[1];
    const float* priors = (const float*)d_in[2];
    const float* means  = (const float*)d_in[3];
    const float* scales = (const float*)d_in[4];

    int smem = 1024 + 2 * NS * SP * 2;   // wbuf + two G buffers
    cudaFuncSetAttribute(comp_kernel, cudaFuncAttributeMaxDynamicSharedMemorySize, smem);

    prep_kernel<<<NS, 128>>>(trans, priors, means, scales);
    emis_kernel<<<2048, 256>>>(X);
    off_kernel<<<NB, 256>>>();
    comp_kernel<<<NB * NCH, 128, smem>>>();
    comb_kernel<<<NB, 128>>>();
    fin_kernel<<<1, 32>>>((float*)d_out);
}